// round 7
// baseline (speedup 1.0000x reference)
#include <cuda_runtime.h>

// LIF recurrence: v = alpha*v + beta*c; spike = (v >= 1); v = spike ? 0 : v.
// T sequential steps (loop-carried), N independent neurons.
//
// R5: float2 vectorization on top of R4's double-buffered pipeline.
// R4 measured 74% DRAM; model says scalar LSU issue (1 LDG.32 + 2 STG.32 per
// step per thread -> ~167k cyc/SM ~ 87us) was stretching the compute phases.
// float2 halves warp-level LSU ops (STG.64=7.75 vs 2x5, LDG count halved),
// gives each thread 2 independent v-chains (ILP in the dependent phase), and
// keeps the same 2 MB chip-wide in-flight load window.

// Bit-identical arithmetic to the reference:
// ALPHA = float(np.exp(-1/20)), BETA = float(1 - ALPHA_double).
#define ALPHA_F ((float)0.95122942450071400910)
#define BETA_F  ((float)0.04877057549928599090)

__device__ __forceinline__ void lif_step2(float2 c, float2& v, float2& s)
{
    v.x = fmaf(ALPHA_F, v.x, BETA_F * c.x);
    v.y = fmaf(ALPHA_F, v.y, BETA_F * c.y);
    const bool spx = (v.x >= 1.0f);
    const bool spy = (v.y >= 1.0f);
    s.x = spx ? 1.0f : 0.0f;
    s.y = spy ? 1.0f : 0.0f;
    v.x = spx ? 0.0f : v.x;     // V_RESET = 0
    v.y = spy ? 0.0f : v.y;
}

// T steps, N2 = N/2 float2 columns, U-deep double buffer.
template<int T, int N2, int U>
__global__ void __launch_bounds__(32)
lif_v2(const float2* __restrict__ cur, const float2* __restrict__ v0,
       float2* __restrict__ spikes, float2* __restrict__ volts)
{
    const int n = blockIdx.x * blockDim.x + threadIdx.x;   // float2-column index
    float2 v = v0[n];

    const float2* p  = cur    + n;
    float2*       ps = spikes + n;
    float2*       pv = volts  + n;

    static_assert(T % U == 0 && (T / U) % 2 == 0, "need even block count");
    constexpr int ITERS = T / U;

    float2 a[U], b[U];

    // Prologue: fill both buffers.
#pragma unroll
    for (int u = 0; u < U; ++u) a[u] = __ldcs(p + (size_t)u * N2);
#pragma unroll
    for (int u = 0; u < U; ++u) b[u] = __ldcs(p + (size_t)(U + u) * N2);
    p += (size_t)2 * U * N2;

    // Main: compute A (B in flight), refill A, compute B (A in flight), refill B.
    for (int it = 0; it < ITERS - 2; it += 2) {
#pragma unroll
        for (int u = 0; u < U; ++u) {
            float2 s;
            lif_step2(a[u], v, s);
            __stcs(ps + (size_t)u * N2, s);
            __stcs(pv + (size_t)u * N2, v);
        }
        ps += (size_t)U * N2;  pv += (size_t)U * N2;
#pragma unroll
        for (int u = 0; u < U; ++u) a[u] = __ldcs(p + (size_t)u * N2);
        p += (size_t)U * N2;

#pragma unroll
        for (int u = 0; u < U; ++u) {
            float2 s;
            lif_step2(b[u], v, s);
            __stcs(ps + (size_t)u * N2, s);
            __stcs(pv + (size_t)u * N2, v);
        }
        ps += (size_t)U * N2;  pv += (size_t)U * N2;
#pragma unroll
        for (int u = 0; u < U; ++u) b[u] = __ldcs(p + (size_t)u * N2);
        p += (size_t)U * N2;
    }

    // Epilogue: last two blocks, no refills.
#pragma unroll
    for (int u = 0; u < U; ++u) {
        float2 s;
        lif_step2(a[u], v, s);
        __stcs(ps + (size_t)u * N2, s);
        __stcs(pv + (size_t)u * N2, v);
    }
    ps += (size_t)U * N2;  pv += (size_t)U * N2;
#pragma unroll
    for (int u = 0; u < U; ++u) {
        float2 s;
        lif_step2(b[u], v, s);
        __stcs(ps + (size_t)u * N2, s);
        __stcs(pv + (size_t)u * N2, v);
    }
}

// Generic fallback (any T, N).
__global__ void lif_generic(const float* __restrict__ cur, const float* __restrict__ v0,
                            float* __restrict__ spikes, float* __restrict__ volts,
                            int T, int N)
{
    int n = blockIdx.x * blockDim.x + threadIdx.x;
    if (n >= N) return;
    float v = v0[n];
    size_t idx = (size_t)n;
    for (int t = 0; t < T; ++t) {
        float c = __ldcs(cur + idx);
        v = fmaf(ALPHA_F, v, BETA_F * c);
        const bool sp = (v >= 1.0f);
        __stcs(spikes + idx, sp ? 1.0f : 0.0f);
        v = sp ? 0.0f : v;
        __stcs(volts + idx, v);
        idx += (size_t)N;
    }
}

extern "C" void kernel_launch(void* const* d_in, const int* in_sizes, int n_in,
                              void* d_out, int out_size)
{
    // metadata order: currents (T*N), v0 (N)
    const float* cur = (const float*)d_in[0];
    const float* v0  = (const float*)d_in[1];

    const int N = in_sizes[1];
    const int T = in_sizes[0] / N;

    float* out    = (float*)d_out;
    float* spikes = out;                          // first T*N elements
    float* volts  = out + (size_t)T * (size_t)N;  // second T*N elements

    if (T == 2048 && N == 32768) {
        // 16384 float2-threads -> 512 blocks of 32 (3.46 warps/SM, single wave).
        lif_v2<2048, 16384, 16><<<512, 32>>>(
            (const float2*)cur, (const float2*)v0,
            (float2*)spikes, (float2*)volts);
    } else {
        const int threads = 128;
        lif_generic<<<(N + threads - 1) / threads, threads>>>(cur, v0, spikes, volts, T, N);
    }
}

// round 8
// speedup vs baseline: 1.1105x; 1.1105x over previous
#include <cuda_runtime.h>

// LIF recurrence: v = alpha*v + beta*c; spike = (v >= 1); v = spike ? 0 : v.
//
// R7: scalar one-thread-per-neuron (1024 warps) with a 4-buffer x U=16 load
// ring. Cross-round evidence: DRAM% tracks chip-wide in-flight load bytes
// (R3 2MB->53%, R4 4MB->74%, R5 2MB->67%). float2 halved warps AND buffer
// depth -> regression. This round keeps 1024 warps, raises steady-state
// in-flight to ~6MB, and triples the prefetch distance (loads issued 3
// compute-phases before consumption, ~1200+ cyc) so loaded-DRAM latency
// (~600-900 cyc) is fully covered.

// Bit-identical arithmetic to the reference:
// ALPHA = float(np.exp(-1/20)), BETA = float(1 - ALPHA_double).
#define ALPHA_F ((float)0.95122942450071400910)
#define BETA_F  ((float)0.04877057549928599090)

template<int T, int N, int U>
__global__ void __launch_bounds__(32)
lif_quad(const float* __restrict__ cur, const float* __restrict__ v0,
         float* __restrict__ spikes, float* __restrict__ volts)
{
    const int n = blockIdx.x * blockDim.x + threadIdx.x;   // one thread per neuron
    float v = v0[n];

    const float* p  = cur    + n;
    float*       ps = spikes + n;
    float*       pv = volts  + n;

    static_assert(T % U == 0 && (T / U) % 4 == 0, "phase count must divide by 4");
    constexpr int ITERS = T / U;   // 128 for T=2048, U=16

    float buf[4][U];

    // Prologue: fill all 4 ring slots (phases 0..3).
#pragma unroll
    for (int k = 0; k < 4; ++k)
#pragma unroll
        for (int u = 0; u < U; ++u)
            buf[k][u] = __ldcs(p + (size_t)(k * U + u) * N);
    p += (size_t)4 * U * N;        // next load = phase 4

    // Main loop: groups of 4 phases. Compute slot k, then refill it with the
    // phase 4 ahead -> 3 full compute phases between a load and its consumer.
    for (int i = 0; i < ITERS - 4; i += 4) {
#pragma unroll
        for (int k = 0; k < 4; ++k) {
#pragma unroll
            for (int u = 0; u < U; ++u) {
                v = fmaf(ALPHA_F, v, BETA_F * buf[k][u]);
                const bool sp = (v >= 1.0f);
                __stcs(ps + (size_t)u * N, sp ? 1.0f : 0.0f);
                v = sp ? 0.0f : v;                 // V_RESET = 0
                __stcs(pv + (size_t)u * N, v);
            }
            ps += (size_t)U * N;  pv += (size_t)U * N;
#pragma unroll
            for (int u = 0; u < U; ++u)
                buf[k][u] = __ldcs(p + (size_t)u * N);
            p += (size_t)U * N;
        }
    }

    // Epilogue: last 4 phases, no refills.
#pragma unroll
    for (int k = 0; k < 4; ++k) {
#pragma unroll
        for (int u = 0; u < U; ++u) {
            v = fmaf(ALPHA_F, v, BETA_F * buf[k][u]);
            const bool sp = (v >= 1.0f);
            __stcs(ps + (size_t)u * N, sp ? 1.0f : 0.0f);
            v = sp ? 0.0f : v;
            __stcs(pv + (size_t)u * N, v);
        }
        ps += (size_t)U * N;  pv += (size_t)U * N;
    }
}

// Generic fallback (any T, N).
__global__ void lif_generic(const float* __restrict__ cur, const float* __restrict__ v0,
                            float* __restrict__ spikes, float* __restrict__ volts,
                            int T, int N)
{
    int n = blockIdx.x * blockDim.x + threadIdx.x;
    if (n >= N) return;
    float v = v0[n];
    size_t idx = (size_t)n;
    for (int t = 0; t < T; ++t) {
        float c = __ldcs(cur + idx);
        v = fmaf(ALPHA_F, v, BETA_F * c);
        const bool sp = (v >= 1.0f);
        __stcs(spikes + idx, sp ? 1.0f : 0.0f);
        v = sp ? 0.0f : v;
        __stcs(volts + idx, v);
        idx += (size_t)N;
    }
}

extern "C" void kernel_launch(void* const* d_in, const int* in_sizes, int n_in,
                              void* d_out, int out_size)
{
    // metadata order: currents (T*N), v0 (N)
    const float* cur = (const float*)d_in[0];
    const float* v0  = (const float*)d_in[1];

    const int N = in_sizes[1];
    const int T = in_sizes[0] / N;

    float* out    = (float*)d_out;
    float* spikes = out;                          // first T*N elements
    float* volts  = out + (size_t)T * (size_t)N;  // second T*N elements

    if (T == 2048 && N == 32768) {
        // 1024 blocks x 32 threads = 1024 warps (~7/SM), single wave.
        lif_quad<2048, 32768, 16><<<1024, 32>>>(cur, v0, spikes, volts);
    } else {
        const int threads = 128;
        lif_generic<<<(N + threads - 1) / threads, threads>>>(cur, v0, spikes, volts, T, N);
    }
}